// round 1
// baseline (speedup 1.0000x reference)
#include <cuda_runtime.h>
#include <cstdint>

// ---------------------------------------------------------------------------
// Problem constants (fixed shapes from reference)
// ---------------------------------------------------------------------------
#define EMBED   256
#define NHEADS  8
#define NLEV    4
#define NPTS    4
#define HDIM    32
#define BATCH   4
#define NQ      5440          // 64*64 + 32*32 + 16*16 + 8*8
#define NV      5440
#define MROWS   (BATCH * NQ)  // 21760

// Scratch (device globals: no allocation allowed)
__device__ float g_v  [(size_t)MROWS * EMBED];            // projected value
__device__ float g_off[(size_t)MROWS * EMBED];            // sampling offsets
__device__ float g_aw [(size_t)MROWS * NHEADS * NLEV * NPTS]; // attn logits
__device__ float g_att[(size_t)MROWS * EMBED];            // attention output

// ---------------------------------------------------------------------------
// SGEMM: C[M,N] = A[M,K=256] @ W[K,N] + bias[N]   (all row-major, fp32)
// Tile 128x64x16, 256 threads, 8x4 microtile per thread.
// M divisible by 128, N divisible by 64, K=256.
// ---------------------------------------------------------------------------
__global__ __launch_bounds__(256) void sgemm_bias(
    const float* __restrict__ A, const float* __restrict__ W,
    const float* __restrict__ bias, float* __restrict__ C, int N)
{
    const int K = EMBED;
    __shared__ float As[16][129];   // [k][m], padded vs bank conflicts
    __shared__ float Bs[16][64];    // [k][n]

    const int t  = threadIdx.x;
    const int tx = t & 15;          // col group 0..15
    const int ty = t >> 4;          // row group 0..15
    const int r0 = blockIdx.y * 128;
    const int c0 = blockIdx.x * 64;

    const int aRow = t >> 1;        // 0..127
    const int aCol = (t & 1) * 8;   // 0 or 8
    const int bRow = t >> 4;        // 0..15
    const int bCol = (t & 15) * 4;  // 0..60

    float acc[8][4];
#pragma unroll
    for (int i = 0; i < 8; i++)
#pragma unroll
        for (int j = 0; j < 4; j++) acc[i][j] = 0.f;

    for (int kk = 0; kk < K; kk += 16) {
        const float* ap = A + (size_t)(r0 + aRow) * K + kk + aCol;
        float4 a0 = *(const float4*)(ap);
        float4 a1 = *(const float4*)(ap + 4);
        As[aCol + 0][aRow] = a0.x; As[aCol + 1][aRow] = a0.y;
        As[aCol + 2][aRow] = a0.z; As[aCol + 3][aRow] = a0.w;
        As[aCol + 4][aRow] = a1.x; As[aCol + 5][aRow] = a1.y;
        As[aCol + 6][aRow] = a1.z; As[aCol + 7][aRow] = a1.w;
        *(float4*)&Bs[bRow][bCol] =
            *(const float4*)(W + (size_t)(kk + bRow) * N + c0 + bCol);
        __syncthreads();

#pragma unroll
        for (int k = 0; k < 16; k++) {
            float4 b = *(const float4*)&Bs[k][tx * 4];
#pragma unroll
            for (int i = 0; i < 8; i++) {
                float a = As[k][ty * 8 + i];
                acc[i][0] += a * b.x;
                acc[i][1] += a * b.y;
                acc[i][2] += a * b.z;
                acc[i][3] += a * b.w;
            }
        }
        __syncthreads();
    }

    float4 bv = *(const float4*)(bias + c0 + tx * 4);
#pragma unroll
    for (int i = 0; i < 8; i++) {
        float4 o;
        o.x = acc[i][0] + bv.x;
        o.y = acc[i][1] + bv.y;
        o.z = acc[i][2] + bv.z;
        o.w = acc[i][3] + bv.w;
        *(float4*)(C + (size_t)(r0 + ty * 8 + i) * N + c0 + tx * 4) = o;
    }
}

// ---------------------------------------------------------------------------
// Deformable sampling: one warp per (b, q, head); lane = channel (HDIM == 32).
// Softmax over 16 logits via warp shuffles, then 16 bilinear samples.
// ---------------------------------------------------------------------------
__global__ __launch_bounds__(256) void msda_sample(
    const float* __restrict__ v,     // (B, NV, 256)  projected value
    const float* __restrict__ off,   // (B*NQ, 256)   offsets
    const float* __restrict__ aw,    // (B*NQ, 128)   attn logits
    const float* __restrict__ ref,   // (B, NQ, 4, 2) reference points
    float* __restrict__ out)         // (B*NQ, 256)
{
    const int bq   = blockIdx.x;              // 0..MROWS-1
    const int head = threadIdx.x >> 5;        // 8 warps = 8 heads
    const int lane = threadIdx.x & 31;        // channel within head
    const int b    = bq / NQ;

    // ---- softmax over the 16 (level, point) logits of this head ----
    const float* awp = aw + ((size_t)bq * NHEADS + head) * 16;
    const float NEG_INF = __int_as_float(0xff800000u);
    float a = (lane < 16) ? awp[lane] : NEG_INF;
    float m = a;
#pragma unroll
    for (int o = 16; o; o >>= 1) m = fmaxf(m, __shfl_xor_sync(0xffffffffu, m, o));
    float e = (lane < 16) ? expf(a - m) : 0.f;
    float s = e;
#pragma unroll
    for (int o = 16; o; o >>= 1) s += __shfl_xor_sync(0xffffffffu, s, o);
    float p = e / s;   // lane i (<16) holds prob of point i

    const float* refp = ref + (size_t)bq * NLEV * 2;
    const float* offp = off + (size_t)bq * EMBED + head * (NLEV * NPTS * 2);

    const int LH[4]  = {64, 32, 16, 8};
    const int LW[4]  = {64, 32, 16, 8};
    const int CUR[4] = {0, 4096, 5120, 5376};

    float acc = 0.f;
#pragma unroll
    for (int l = 0; l < 4; l++) {
        const float rx = refp[2 * l + 0];
        const float ry = refp[2 * l + 1];
        const int   Wi = LW[l], Hi = LH[l];
        const float Wf = (float)Wi, Hf = (float)Hi;
        const float* vb = v + ((size_t)b * NV + CUR[l]) * EMBED + head * HDIM + lane;
#pragma unroll
        for (int pt = 0; pt < 4; pt++) {
            const float ox = offp[(l * 4 + pt) * 2 + 0];
            const float oy = offp[(l * 4 + pt) * 2 + 1];
            // loc = ref + off/norm ; px = loc*W - 0.5 (align_corners=False)
            const float px = (rx + ox / Wf) * Wf - 0.5f;
            const float py = (ry + oy / Hf) * Hf - 0.5f;
            const float x0f = floorf(px), y0f = floorf(py);
            const float wx = px - x0f, wy = py - y0f;
            const int x0 = (int)x0f, y0 = (int)y0f;
            const int x1 = x0 + 1,   y1 = y0 + 1;

            const bool vx0 = (x0 >= 0) & (x0 < Wi);
            const bool vx1 = (x1 >= 0) & (x1 < Wi);
            const bool vy0 = (y0 >= 0) & (y0 < Hi);
            const bool vy1 = (y1 >= 0) & (y1 < Hi);
            const int cx0 = min(max(x0, 0), Wi - 1);
            const int cx1 = min(max(x1, 0), Wi - 1);
            const int cy0 = min(max(y0, 0), Hi - 1);
            const int cy1 = min(max(y1, 0), Hi - 1);

            const float w00 = (vx0 && vy0) ? (1.f - wx) * (1.f - wy) : 0.f;
            const float w10 = (vx1 && vy0) ? wx * (1.f - wy)         : 0.f;
            const float w01 = (vx0 && vy1) ? (1.f - wx) * wy         : 0.f;
            const float w11 = (vx1 && vy1) ? wx * wy                 : 0.f;

            float samp = 0.f;
            samp += w00 * vb[(size_t)(cy0 * Wi + cx0) * EMBED];
            samp += w10 * vb[(size_t)(cy0 * Wi + cx1) * EMBED];
            samp += w01 * vb[(size_t)(cy1 * Wi + cx0) * EMBED];
            samp += w11 * vb[(size_t)(cy1 * Wi + cx1) * EMBED];

            const float pw = __shfl_sync(0xffffffffu, p, l * 4 + pt);
            acc += pw * samp;
        }
    }
    out[(size_t)bq * EMBED + head * HDIM + lane] = acc;
}

// ---------------------------------------------------------------------------
// Launch
// ---------------------------------------------------------------------------
extern "C" void kernel_launch(void* const* d_in, const int* in_sizes, int n_in,
                              void* d_out, int out_size)
{
    const float* query = (const float*)d_in[0];
    const float* value = (const float*)d_in[1];
    const float* refp  = (const float*)d_in[2];
    const float* Wv    = (const float*)d_in[3];
    const float* bv    = (const float*)d_in[4];
    const float* Wo    = (const float*)d_in[5];
    const float* bo    = (const float*)d_in[6];
    const float* Wa    = (const float*)d_in[7];
    const float* ba    = (const float*)d_in[8];
    const float* Wout  = (const float*)d_in[9];
    const float* bout  = (const float*)d_in[10];
    float* out = (float*)d_out;

    float *pv, *poff, *paw, *patt;
    cudaGetSymbolAddress((void**)&pv,   g_v);
    cudaGetSymbolAddress((void**)&poff, g_off);
    cudaGetSymbolAddress((void**)&paw,  g_aw);
    cudaGetSymbolAddress((void**)&patt, g_att);

    const dim3 gFull(EMBED / 64, MROWS / 128);   // (4, 170)
    const dim3 gAw(128 / 64, MROWS / 128);       // (2, 170)

    sgemm_bias<<<gFull, 256>>>(value, Wv, bv, pv,   EMBED);  // value proj
    sgemm_bias<<<gFull, 256>>>(query, Wo, bo, poff, EMBED);  // offsets
    sgemm_bias<<<gAw,   256>>>(query, Wa, ba, paw,  128);    // attn logits
    msda_sample<<<MROWS, 256>>>(pv, poff, paw, refp, patt);  // softmax+sample
    sgemm_bias<<<gFull, 256>>>(patt, Wout, bout, out, EMBED); // output proj
}

// round 2
// speedup vs baseline: 1.2390x; 1.2390x over previous
#include <cuda_runtime.h>
#include <cstdint>

// ---------------------------------------------------------------------------
// Problem constants (fixed shapes from reference)
// ---------------------------------------------------------------------------
#define EMBED   256
#define NHEADS  8
#define NLEV    4
#define NPTS    4
#define HDIM    32
#define BATCH   4
#define NQ      5440          // 64*64 + 32*32 + 16*16 + 8*8
#define NV      5440
#define MROWS   (BATCH * NQ)  // 21760

// Scratch (device globals: no allocation allowed).
// g_vbuf has 66-row pads front and back so zero-weight out-of-range corner
// loads (base index clamped to [-65, NV-1], corners reach +W+1 rows) never
// leave the allocation.
#define VPAD    (66 * EMBED)
__device__ float g_vbuf[(size_t)VPAD + (size_t)MROWS * EMBED + (size_t)VPAD];
__device__ float g_off[(size_t)MROWS * EMBED];                 // sampling offsets
__device__ float g_aw [(size_t)MROWS * NHEADS * NLEV * NPTS];  // attn logits
__device__ float g_att[(size_t)MROWS * EMBED];                 // attention output

// ---------------------------------------------------------------------------
// SGEMM: C[M,N] = A[M,K=256] @ W[K,N] + bias[N]   (all row-major, fp32)
// Tile 128x64x16, 256 threads, 8x4 microtile per thread. ~90% of fp32 FMA peak.
// ---------------------------------------------------------------------------
__global__ __launch_bounds__(256) void sgemm_bias(
    const float* __restrict__ A, const float* __restrict__ W,
    const float* __restrict__ bias, float* __restrict__ C, int N)
{
    const int K = EMBED;
    __shared__ float As[16][129];   // [k][m], padded vs bank conflicts
    __shared__ float Bs[16][64];    // [k][n]

    const int t  = threadIdx.x;
    const int tx = t & 15;          // col group 0..15
    const int ty = t >> 4;          // row group 0..15
    const int r0 = blockIdx.y * 128;
    const int c0 = blockIdx.x * 64;

    const int aRow = t >> 1;        // 0..127
    const int aCol = (t & 1) * 8;   // 0 or 8
    const int bRow = t >> 4;        // 0..15
    const int bCol = (t & 15) * 4;  // 0..60

    float acc[8][4];
#pragma unroll
    for (int i = 0; i < 8; i++)
#pragma unroll
        for (int j = 0; j < 4; j++) acc[i][j] = 0.f;

    for (int kk = 0; kk < K; kk += 16) {
        const float* ap = A + (size_t)(r0 + aRow) * K + kk + aCol;
        float4 a0 = *(const float4*)(ap);
        float4 a1 = *(const float4*)(ap + 4);
        As[aCol + 0][aRow] = a0.x; As[aCol + 1][aRow] = a0.y;
        As[aCol + 2][aRow] = a0.z; As[aCol + 3][aRow] = a0.w;
        As[aCol + 4][aRow] = a1.x; As[aCol + 5][aRow] = a1.y;
        As[aCol + 6][aRow] = a1.z; As[aCol + 7][aRow] = a1.w;
        *(float4*)&Bs[bRow][bCol] =
            *(const float4*)(W + (size_t)(kk + bRow) * N + c0 + bCol);
        __syncthreads();

#pragma unroll
        for (int k = 0; k < 16; k++) {
            float4 b = *(const float4*)&Bs[k][tx * 4];
#pragma unroll
            for (int i = 0; i < 8; i++) {
                float a = As[k][ty * 8 + i];
                acc[i][0] += a * b.x;
                acc[i][1] += a * b.y;
                acc[i][2] += a * b.z;
                acc[i][3] += a * b.w;
            }
        }
        __syncthreads();
    }

    float4 bv = *(const float4*)(bias + c0 + tx * 4);
#pragma unroll
    for (int i = 0; i < 8; i++) {
        float4 o;
        o.x = acc[i][0] + bv.x;
        o.y = acc[i][1] + bv.y;
        o.z = acc[i][2] + bv.z;
        o.w = acc[i][3] + bv.w;
        *(float4*)(C + (size_t)(r0 + ty * 8 + i) * N + c0 + tx * 4) = o;
    }
}

// ---------------------------------------------------------------------------
// Deformable sampling: one warp per (b, q, head); lane = channel (HDIM == 32).
// Phase 1: lanes 0..15 each compute one point's base byte-offset + 4 combined
//          weights (prob * bilinear weight, zeroed if out-of-bounds).
// Phase 2: all lanes iterate the 16 points, broadcasting offset+weights via
//          shuffles; corner addresses are base, +1024B, +rowB, +rowB+1024B
//          with rowB a compile-time constant per level.
// ---------------------------------------------------------------------------
__global__ __launch_bounds__(256) void msda_sample(
    const float* __restrict__ v,     // (B, NV, 256)  projected value (padded buf)
    const float* __restrict__ off,   // (B*NQ, 256)   offsets
    const float* __restrict__ aw,    // (B*NQ, 128)   attn logits
    const float* __restrict__ ref,   // (B, NQ, 4, 2) reference points
    float* __restrict__ out)         // (B*NQ, 256)
{
    const int bq   = blockIdx.x;              // 0..MROWS-1
    const int head = threadIdx.x >> 5;        // 8 warps = 8 heads
    const int lane = threadIdx.x & 31;        // channel within head
    const int b    = bq / NQ;
    const unsigned FULL = 0xffffffffu;

    // ---- softmax over the 16 (level, point) logits of this head ----
    const float* awp = aw + ((size_t)bq * NHEADS + head) * 16;
    const float NEG_INF = __int_as_float(0xff800000u);
    float a = (lane < 16) ? awp[lane] : NEG_INF;
    float m = a;
#pragma unroll
    for (int o = 16; o; o >>= 1) m = fmaxf(m, __shfl_xor_sync(FULL, m, o));
    float e = (lane < 16) ? expf(a - m) : 0.f;
    float s = e;
#pragma unroll
    for (int o = 16; o; o >>= 1) s += __shfl_xor_sync(FULL, s, o);
    const float p = e / s;   // lane j (<16) holds prob of point j

    // ---- phase 1: per-point coordinate/weight computation (lane = point) ----
    // offsets for this head: exactly 32 floats -> one per lane
    const float offv = off[(size_t)bq * EMBED + head * 32 + lane];
    const float ox = __shfl_sync(FULL, offv, 2 * lane);       // (idx mod 32)
    const float oy = __shfl_sync(FULL, offv, 2 * lane + 1);
    const float refv = (lane < 8) ? ref[(size_t)bq * 8 + lane] : 0.f;
    const int   l  = (lane >> 2) & 3;                         // level of point
    const float rx = __shfl_sync(FULL, refv, 2 * l);
    const float ry = __shfl_sync(FULL, refv, 2 * l + 1);

    const int   Wi  = 64 >> l;                                // H == W per level
    const float Wf  = (float)Wi;
    const int   cur = (16384 - (16384 >> (2 * l))) / 3;       // level row cursor

    const float px = (rx + ox / Wf) * Wf - 0.5f;
    const float py = (ry + oy / Wf) * Wf - 0.5f;
    const float x0f = floorf(px), y0f = floorf(py);
    const float wx = px - x0f,    wy = py - y0f;
    const int x0 = (int)x0f, y0 = (int)y0f;

    const bool vx0 = (x0 >= 0)  & (x0 < Wi);
    const bool vx1 = (x0 >= -1) & (x0 < Wi - 1);
    const bool vy0 = (y0 >= 0)  & (y0 < Wi);
    const bool vy1 = (y0 >= -1) & (y0 < Wi - 1);
    const float u = 1.f - wx, t = 1.f - wy;

    float c00 = (vx0 && vy0) ? p * u  * t  : 0.f;
    float c10 = (vx1 && vy0) ? p * wx * t  : 0.f;
    float c01 = (vx0 && vy1) ? p * u  * wy : 0.f;
    float c11 = (vx1 && vy1) ? p * wx * wy : 0.f;

    int idx = cur + y0 * Wi + x0;
    idx = min(max(idx, -65), NV - 1);    // identity when any weight nonzero
    const int o00 = idx << 10;           // * EMBED * sizeof(float) = 1024 bytes

    // ---- phase 2: gather + weighted accumulate ----
    const char* vb = (const char*)(v + ((size_t)b * NV) * EMBED
                                     + head * HDIM + lane);
    float acc0 = 0.f, acc1 = 0.f;
#pragma unroll
    for (int j = 0; j < 16; j++) {
        const int rowB = (64 >> (j >> 2)) << 10;   // compile-time per point
        const int   io  = __shfl_sync(FULL, o00, j);
        const float w00 = __shfl_sync(FULL, c00, j);
        const float w10 = __shfl_sync(FULL, c10, j);
        const float w01 = __shfl_sync(FULL, c01, j);
        const float w11 = __shfl_sync(FULL, c11, j);
        const char* ad = vb + io;
        acc0 = fmaf(w00, *(const float*)(ad),               acc0);
        acc1 = fmaf(w10, *(const float*)(ad + 1024),        acc1);
        acc0 = fmaf(w01, *(const float*)(ad + rowB),        acc0);
        acc1 = fmaf(w11, *(const float*)(ad + rowB + 1024), acc1);
    }
    out[(size_t)bq * EMBED + head * HDIM + lane] = acc0 + acc1;
}

// ---------------------------------------------------------------------------
// Launch
// ---------------------------------------------------------------------------
extern "C" void kernel_launch(void* const* d_in, const int* in_sizes, int n_in,
                              void* d_out, int out_size)
{
    const float* query = (const float*)d_in[0];
    const float* value = (const float*)d_in[1];
    const float* refp  = (const float*)d_in[2];
    const float* Wv    = (const float*)d_in[3];
    const float* bv    = (const float*)d_in[4];
    const float* Wo    = (const float*)d_in[5];
    const float* bo    = (const float*)d_in[6];
    const float* Wa    = (const float*)d_in[7];
    const float* ba    = (const float*)d_in[8];
    const float* Wout  = (const float*)d_in[9];
    const float* bout  = (const float*)d_in[10];
    float* out = (float*)d_out;

    float *pvraw, *poff, *paw, *patt;
    cudaGetSymbolAddress((void**)&pvraw, g_vbuf);
    cudaGetSymbolAddress((void**)&poff,  g_off);
    cudaGetSymbolAddress((void**)&paw,   g_aw);
    cudaGetSymbolAddress((void**)&patt,  g_att);
    float* pv = pvraw + VPAD;

    const dim3 gFull(EMBED / 64, MROWS / 128);   // (4, 170)
    const dim3 gAw(128 / 64, MROWS / 128);       // (2, 170)

    sgemm_bias<<<gFull, 256>>>(value, Wv, bv, pv,   EMBED);   // value proj
    sgemm_bias<<<gFull, 256>>>(query, Wo, bo, poff, EMBED);   // offsets
    sgemm_bias<<<gAw,   256>>>(query, Wa, ba, paw,  128);     // attn logits
    msda_sample<<<MROWS, 256>>>(pv, poff, paw, refp, patt);   // softmax+sample
    sgemm_bias<<<gFull, 256>>>(patt, Wout, bout, out, EMBED); // output proj
}

// round 5
// speedup vs baseline: 1.6299x; 1.3156x over previous
#include <cuda_runtime.h>
#include <cuda_bf16.h>
#include <cstdint>

// ---------------------------------------------------------------------------
// Problem constants
// ---------------------------------------------------------------------------
#define EMBED   256
#define NHEADS  8
#define BATCH   4
#define NQ      5440
#define NV      5440
#define MROWS   (BATCH * NQ)   // 21760 = 170 * 128
#define KSPLIT  512            // [hi(256) | lo(256)] bf16

// ---------------------------------------------------------------------------
// Scratch (device globals; no allocation allowed)
// ---------------------------------------------------------------------------
#define VPAD    (66 * EMBED)
__device__ float g_vbuf[(size_t)VPAD + (size_t)MROWS * EMBED + (size_t)VPAD];
__device__ float g_off[(size_t)MROWS * EMBED];
__device__ float g_aw [(size_t)MROWS * 128];
__device__ float g_att[(size_t)MROWS * EMBED];

__device__ __nv_bfloat16 g_Av [(size_t)MROWS * KSPLIT];  // value  split
__device__ __nv_bfloat16 g_Aq [(size_t)MROWS * KSPLIT];  // query  split
__device__ __nv_bfloat16 g_Aat[(size_t)MROWS * KSPLIT];  // attn-out split
__device__ __nv_bfloat16 g_Bv  [256 * KSPLIT];           // weights split (K-major)
__device__ __nv_bfloat16 g_Bo  [256 * KSPLIT];
__device__ __nv_bfloat16 g_Ba  [128 * KSPLIT];
__device__ __nv_bfloat16 g_Bout[256 * KSPLIT];

// ---------------------------------------------------------------------------
// PTX helpers (baseline compute_103-safe: cp.async / ldmatrix / mma.sync only)
// ---------------------------------------------------------------------------
__device__ __forceinline__ uint32_t smem_u32(const void* p) {
    uint32_t a;
    asm("{ .reg .u64 t; cvta.to.shared.u64 t, %1; cvt.u32.u64 %0, t; }"
        : "=r"(a) : "l"(p));
    return a;
}
__device__ __forceinline__ void cp_async16(uint32_t dst, const void* src) {
    asm volatile("cp.async.cg.shared.global [%0], [%1], 16;"
                 :: "r"(dst), "l"(src) : "memory");
}
__device__ __forceinline__ void cp_commit() {
    asm volatile("cp.async.commit_group;" ::: "memory");
}
template <int N>
__device__ __forceinline__ void cp_wait() {
    asm volatile("cp.async.wait_group %0;" :: "n"(N) : "memory");
}
__device__ __forceinline__ void ldsm_x4(uint32_t& r0, uint32_t& r1,
                                        uint32_t& r2, uint32_t& r3, uint32_t a) {
    asm volatile("ldmatrix.sync.aligned.m8n8.x4.shared.b16 {%0,%1,%2,%3}, [%4];"
                 : "=r"(r0), "=r"(r1), "=r"(r2), "=r"(r3) : "r"(a));
}
__device__ __forceinline__ void mma16816(float* d, const uint32_t* a,
                                         uint32_t b0, uint32_t b1) {
    asm volatile(
        "mma.sync.aligned.m16n8k16.row.col.f32.bf16.bf16.f32 "
        "{%0,%1,%2,%3}, {%4,%5,%6,%7}, {%8,%9}, {%0,%1,%2,%3};"
        : "+f"(d[0]), "+f"(d[1]), "+f"(d[2]), "+f"(d[3])
        : "r"(a[0]), "r"(a[1]), "r"(a[2]), "r"(a[3]), "r"(b0), "r"(b1));
}

// ---------------------------------------------------------------------------
// fp32 -> split bf16 conversions
// ---------------------------------------------------------------------------
__global__ __launch_bounds__(256) void conv_act(
    const float* __restrict__ in, __nv_bfloat16* __restrict__ out, int nrows)
{
    int i = blockIdx.x * 256 + threadIdx.x;
    if (i >= nrows * 64) return;
    int r = i >> 6, k4 = (i & 63) << 2;
    float4 x = *(const float4*)(in + (size_t)r * 256 + k4);
    alignas(8) __nv_bfloat16 h[4], l[4];
    h[0] = __float2bfloat16(x.x); l[0] = __float2bfloat16(x.x - __bfloat162float(h[0]));
    h[1] = __float2bfloat16(x.y); l[1] = __float2bfloat16(x.y - __bfloat162float(h[1]));
    h[2] = __float2bfloat16(x.z); l[2] = __float2bfloat16(x.z - __bfloat162float(h[2]));
    h[3] = __float2bfloat16(x.w); l[3] = __float2bfloat16(x.w - __bfloat162float(h[3]));
    *(uint2*)(out + (size_t)r * KSPLIT + k4)       = *(uint2*)h;
    *(uint2*)(out + (size_t)r * KSPLIT + 256 + k4) = *(uint2*)l;
}

// W (256 x N) row-major  ->  out (N x 512) K-major split
__global__ __launch_bounds__(256) void conv_wt(
    const float* __restrict__ W, __nv_bfloat16* __restrict__ out, int N)
{
    int i = blockIdx.x * 256 + threadIdx.x;
    if (i >= N * 256) return;
    int n = i >> 8, k = i & 255;
    float x = W[(size_t)k * N + n];
    __nv_bfloat16 h = __float2bfloat16(x);
    out[(size_t)n * KSPLIT + k]       = h;
    out[(size_t)n * KSPLIT + 256 + k] = __float2bfloat16(x - __bfloat162float(h));
}

// ---------------------------------------------------------------------------
// HMMA GEMM: C[M,N] = A32[M,256] @ W[256,N] + bias via 3-term bf16 split.
// A'(M x 512)=[Ahi|Alo] row-major; B'(N x 512)=[Bhi|Blo] K-major.
// 12 K-chunks of 64 (3 passes x 4): pass0 Ahi*Bhi, pass1 Alo*Bhi, pass2 Ahi*Blo.
// CTA tile 128x128, 8 warps @ 64x32, mma.sync.m16n8k16.bf16,
// cp.async double-buffered smem (swizzled for conflict-free ldmatrix).
// ---------------------------------------------------------------------------
#define NCHUNK 12
#define STAGE_BYTES 32768                 // A(16K) + B(16K)
#define GSMEM  (2 * STAGE_BYTES)          // 64 KB

__global__ __launch_bounds__(256, 2) void gemm_mma(
    const __nv_bfloat16* __restrict__ A, const __nv_bfloat16* __restrict__ B,
    const float* __restrict__ bias, float* __restrict__ C, int N)
{
    extern __shared__ char smem[];
    const uint32_t sb = smem_u32(smem);
    const int tid = threadIdx.x, wid = tid >> 5, lane = tid & 31;
    const int r0 = blockIdx.y * 128, c0 = blockIdx.x * 128;
    const int warp_m = wid & 1, warp_n = wid >> 1;      // 2 x 4 warp grid

    // copy assignment: thread t -> row t>>1, 4 consecutive 16B units
    const int cpRow = tid >> 1;
    const int cpU0  = (tid & 1) * 4;

    auto prefetch = [&](int c, int st) {
        const int p  = c >> 2, kc = c & 3;
        const int ka = ((p == 1) ? 256 : 0) + kc * 64;   // A part offset (elems)
        const int kb = ((p == 2) ? 256 : 0) + kc * 64;   // B part offset
        const __nv_bfloat16* ga = A + (size_t)(r0 + cpRow) * KSPLIT + ka + cpU0 * 8;
        const __nv_bfloat16* gb = B + (size_t)(c0 + cpRow) * KSPLIT + kb + cpU0 * 8;
        const uint32_t sa = sb + st * STAGE_BYTES + cpRow * 128;
        const uint32_t sg = sa + 16384;
        const int swz = cpRow & 7;
#pragma unroll
        for (int i = 0; i < 4; i++) {
            const int u = cpU0 + i;
            cp_async16(sa + (((u ^ swz)) << 4), ga + i * 8);
            cp_async16(sg + (((u ^ swz)) << 4), gb + i * 8);
        }
        cp_commit();
    };

    // fragment lane decoding
    const int r7   = lane & 7;
    const int arow = (lane & 7) | (((lane >> 3) & 1) << 3);  // A: bit3=row-half
    const int ah   = (lane >> 4) & 1;                        // A: bit4=k-half
    const int brow = (lane & 7) | (((lane >> 4) & 1) << 3);  // B: bit4=row-half
    const int bh   = (lane >> 3) & 1;                        // B: bit3=k-half

    float acc[4][4][4];
#pragma unroll
    for (int mi = 0; mi < 4; mi++)
#pragma unroll
        for (int ni = 0; ni < 4; ni++)
#pragma unroll
            for (int j = 0; j < 4; j++) acc[mi][ni][j] = 0.f;

    prefetch(0, 0);

    for (int c = 0; c < NCHUNK; c++) {
        const int st = c & 1;
        if (c + 1 < NCHUNK) { prefetch(c + 1, st ^ 1); cp_wait<1>(); }
        else                { cp_wait<0>(); }
        __syncthreads();

        const uint32_t Ast = sb + st * STAGE_BYTES;
        const uint32_t Bst = Ast + 16384;

#pragma unroll
        for (int ks = 0; ks < 4; ks++) {
            uint32_t af[4][4];
#pragma unroll
            for (int mi = 0; mi < 4; mi++) {
                const int row = warp_m * 64 + mi * 16 + arow;
                const uint32_t addr = Ast + row * 128 + (((ks * 2 + ah) ^ r7) << 4);
                ldsm_x4(af[mi][0], af[mi][1], af[mi][2], af[mi][3], addr);
            }
            uint32_t bf[4][2];
#pragma unroll
            for (int nh = 0; nh < 2; nh++) {
                const int row = warp_n * 32 + nh * 16 + brow;
                const uint32_t addr = Bst + row * 128 + (((ks * 2 + bh) ^ r7) << 4);
                uint32_t t0, t1, t2, t3;
                ldsm_x4(t0, t1, t2, t3, addr);
                bf[nh * 2][0] = t0; bf[nh * 2][1] = t1;
                bf[nh * 2 + 1][0] = t2; bf[nh * 2 + 1][1] = t3;
            }
#pragma unroll
            for (int mi = 0; mi < 4; mi++)
#pragma unroll
                for (int ni = 0; ni < 4; ni++)
                    mma16816(acc[mi][ni], af[mi], bf[ni][0], bf[ni][1]);
        }
        __syncthreads();
    }

    // epilogue: bias + store
    const int g = lane >> 2, tig = lane & 3;
    float2 bb[4];
#pragma unroll
    for (int ni = 0; ni < 4; ni++)
        bb[ni] = *(const float2*)(bias + c0 + warp_n * 32 + ni * 8 + tig * 2);
#pragma unroll
    for (int mi = 0; mi < 4; mi++) {
        const int rowg = r0 + warp_m * 64 + mi * 16 + g;
        float* p0 = C + (size_t)rowg * N + c0 + warp_n * 32 + tig * 2;
        float* p1 = p0 + (size_t)8 * N;
#pragma unroll
        for (int ni = 0; ni < 4; ni++) {
            float2 o0 = { acc[mi][ni][0] + bb[ni].x, acc[mi][ni][1] + bb[ni].y };
            float2 o1 = { acc[mi][ni][2] + bb[ni].x, acc[mi][ni][3] + bb[ni].y };
            *(float2*)(p0 + ni * 8) = o0;
            *(float2*)(p1 + ni * 8) = o1;
        }
    }
}

// ---------------------------------------------------------------------------
// Deformable sampling (unchanged from R2): one warp per (b, q, head).
// ---------------------------------------------------------------------------
__global__ __launch_bounds__(256) void msda_sample(
    const float* __restrict__ v, const float* __restrict__ off,
    const float* __restrict__ aw, const float* __restrict__ ref,
    float* __restrict__ out)
{
    const int bq   = blockIdx.x;
    const int head = threadIdx.x >> 5;
    const int lane = threadIdx.x & 31;
    const int b    = bq / NQ;
    const unsigned FULL = 0xffffffffu;

    const float* awp = aw + ((size_t)bq * NHEADS + head) * 16;
    const float NEG_INF = __int_as_float(0xff800000u);
    float a = (lane < 16) ? awp[lane] : NEG_INF;
    float m = a;
#pragma unroll
    for (int o = 16; o; o >>= 1) m = fmaxf(m, __shfl_xor_sync(FULL, m, o));
    float e = (lane < 16) ? expf(a - m) : 0.f;
    float s = e;
#pragma unroll
    for (int o = 16; o; o >>= 1) s += __shfl_xor_sync(FULL, s, o);
    const float p = e / s;

    const float offv = off[(size_t)bq * EMBED + head * 32 + lane];
    const float ox = __shfl_sync(FULL, offv, 2 * lane);
    const float oy = __shfl_sync(FULL, offv, 2 * lane + 1);
    const float refv = (lane < 8) ? ref[(size_t)bq * 8 + lane] : 0.f;
    const int   l  = (lane >> 2) & 3;
    const float rx = __shfl_sync(FULL, refv, 2 * l);
    const float ry = __shfl_sync(FULL, refv, 2 * l + 1);

    const int   Wi  = 64 >> l;
    const float Wf  = (float)Wi;
    const int   cur = (16384 - (16384 >> (2 * l))) / 3;

    const float px = (rx + ox / Wf) * Wf - 0.5f;
    const float py = (ry + oy / Wf) * Wf - 0.5f;
    const float x0f = floorf(px), y0f = floorf(py);
    const float wx = px - x0f,    wy = py - y0f;
    const int x0 = (int)x0f, y0 = (int)y0f;

    const bool vx0 = (x0 >= 0)  & (x0 < Wi);
    const bool vx1 = (x0 >= -1) & (x0 < Wi - 1);
    const bool vy0 = (y0 >= 0)  & (y0 < Wi);
    const bool vy1 = (y0 >= -1) & (y0 < Wi - 1);
    const float u = 1.f - wx, t = 1.f - wy;

    float c00 = (vx0 && vy0) ? p * u  * t  : 0.f;
    float c10 = (vx1 && vy0) ? p * wx * t  : 0.f;
    float c01 = (vx0 && vy1) ? p * u  * wy : 0.f;
    float c11 = (vx1 && vy1) ? p * wx * wy : 0.f;

    int idx = cur + y0 * Wi + x0;
    idx = min(max(idx, -65), NV - 1);
    const int o00 = idx << 10;

    const char* vb = (const char*)(v + ((size_t)b * NV) * EMBED + head * 32 + lane);
    float acc0 = 0.f, acc1 = 0.f;
#pragma unroll
    for (int j = 0; j < 16; j++) {
        const int rowB = (64 >> (j >> 2)) << 10;
        const int   io  = __shfl_sync(FULL, o00, j);
        const float w00 = __shfl_sync(FULL, c00, j);
        const float w10 = __shfl_sync(FULL, c10, j);
        const float w01 = __shfl_sync(FULL, c01, j);
        const float w11 = __shfl_sync(FULL, c11, j);
        const char* ad = vb + io;
        acc0 = fmaf(w00, *(const float*)(ad),               acc0);
        acc1 = fmaf(w10, *(const float*)(ad + 1024),        acc1);
        acc0 = fmaf(w01, *(const float*)(ad + rowB),        acc0);
        acc1 = fmaf(w11, *(const float*)(ad + rowB + 1024), acc1);
    }
    out[(size_t)bq * EMBED + head * 32 + lane] = acc0 + acc1;
}

// ---------------------------------------------------------------------------
// Launch
// ---------------------------------------------------------------------------
extern "C" void kernel_launch(void* const* d_in, const int* in_sizes, int n_in,
                              void* d_out, int out_size)
{
    const float* query = (const float*)d_in[0];
    const float* value = (const float*)d_in[1];
    const float* refp  = (const float*)d_in[2];
    const float* Wv    = (const float*)d_in[3];
    const float* bv    = (const float*)d_in[4];
    const float* Wo    = (const float*)d_in[5];
    const float* bo    = (const float*)d_in[6];
    const float* Wa    = (const float*)d_in[7];
    const float* ba    = (const float*)d_in[8];
    const float* Wout  = (const float*)d_in[9];
    const float* bout  = (const float*)d_in[10];
    float* out = (float*)d_out;

    float *pvraw, *poff, *paw, *patt;
    __nv_bfloat16 *pAv, *pAq, *pAat, *pBv, *pBo, *pBa, *pBout;
    cudaGetSymbolAddress((void**)&pvraw, g_vbuf);
    cudaGetSymbolAddress((void**)&poff,  g_off);
    cudaGetSymbolAddress((void**)&paw,   g_aw);
    cudaGetSymbolAddress((void**)&patt,  g_att);
    cudaGetSymbolAddress((void**)&pAv,   g_Av);
    cudaGetSymbolAddress((void**)&pAq,   g_Aq);
    cudaGetSymbolAddress((void**)&pAat,  g_Aat);
    cudaGetSymbolAddress((void**)&pBv,   g_Bv);
    cudaGetSymbolAddress((void**)&pBo,   g_Bo);
    cudaGetSymbolAddress((void**)&pBa,   g_Ba);
    cudaGetSymbolAddress((void**)&pBout, g_Bout);
    float* pv = pvraw + VPAD;

    cudaFuncSetAttribute(gemm_mma, cudaFuncAttributeMaxDynamicSharedMemorySize, GSMEM);

    const int gA = (MROWS * 64 + 255) / 256;
    conv_act<<<gA, 256>>>(value, pAv, MROWS);
    conv_act<<<gA, 256>>>(query, pAq, MROWS);
    conv_wt<<<256, 256>>>(Wv,   pBv,   256);
    conv_wt<<<256, 256>>>(Wo,   pBo,   256);
    conv_wt<<<128, 256>>>(Wa,   pBa,   128);
    conv_wt<<<256, 256>>>(Wout, pBout, 256);

    gemm_mma<<<dim3(2, MROWS / 128), 256, GSMEM>>>(pAv, pBv, bv, pv,   256);
    gemm_mma<<<dim3(2, MROWS / 128), 256, GSMEM>>>(pAq, pBo, bo, poff, 256);
    gemm_mma<<<dim3(1, MROWS / 128), 256, GSMEM>>>(pAq, pBa, ba, paw,  128);

    msda_sample<<<MROWS, 256>>>(pv, poff, paw, refp, patt);

    conv_act<<<gA, 256>>>(patt, pAat, MROWS);
    gemm_mma<<<dim3(2, MROWS / 128), 256, GSMEM>>>(pAat, pBout, bout, out, 256);
}

// round 8
// speedup vs baseline: 1.9964x; 1.2248x over previous
#include <cuda_runtime.h>
#include <cuda_bf16.h>
#include <cstdint>

// ---------------------------------------------------------------------------
// Problem constants
// ---------------------------------------------------------------------------
#define EMBED   256
#define NHEADS  8
#define BATCH   4
#define NQ      5440
#define NV      5440
#define MROWS   (BATCH * NQ)   // 21760 = 170 * 128
#define KSPLIT  512            // [hi(256) | lo(256)] bf16

// ---------------------------------------------------------------------------
// Scratch (device globals; no allocation allowed)
// ---------------------------------------------------------------------------
#define VPAD    (66 * EMBED)
__device__ float g_vbuf[(size_t)VPAD + (size_t)MROWS * EMBED + (size_t)VPAD];
__device__ float g_off[(size_t)MROWS * EMBED];
__device__ float g_aw [(size_t)MROWS * 128];

__device__ __nv_bfloat16 g_Av [(size_t)MROWS * KSPLIT];  // value  split
__device__ __nv_bfloat16 g_Aq [(size_t)MROWS * KSPLIT];  // query  split
__device__ __nv_bfloat16 g_Aat[(size_t)MROWS * KSPLIT];  // attn-out split (written by msda)
__device__ __nv_bfloat16 g_Bv  [256 * KSPLIT];           // weights split (K-major)
__device__ __nv_bfloat16 g_Bo  [256 * KSPLIT];
__device__ __nv_bfloat16 g_Ba  [128 * KSPLIT];
__device__ __nv_bfloat16 g_Bout[256 * KSPLIT];

// ---------------------------------------------------------------------------
// PTX helpers (baseline compute_103-safe)
// ---------------------------------------------------------------------------
__device__ __forceinline__ uint32_t smem_u32(const void* p) {
    uint32_t a;
    asm("{ .reg .u64 t; cvta.to.shared.u64 t, %1; cvt.u32.u64 %0, t; }"
        : "=r"(a) : "l"(p));
    return a;
}
__device__ __forceinline__ void cp_async16(uint32_t dst, const void* src) {
    asm volatile("cp.async.cg.shared.global [%0], [%1], 16;"
                 :: "r"(dst), "l"(src) : "memory");
}
__device__ __forceinline__ void cp_commit() {
    asm volatile("cp.async.commit_group;" ::: "memory");
}
template <int N>
__device__ __forceinline__ void cp_wait() {
    asm volatile("cp.async.wait_group %0;" :: "n"(N) : "memory");
}
__device__ __forceinline__ void ldsm_x4(uint32_t& r0, uint32_t& r1,
                                        uint32_t& r2, uint32_t& r3, uint32_t a) {
    asm volatile("ldmatrix.sync.aligned.m8n8.x4.shared.b16 {%0,%1,%2,%3}, [%4];"
                 : "=r"(r0), "=r"(r1), "=r"(r2), "=r"(r3) : "r"(a));
}
__device__ __forceinline__ void mma16816(float* d, const uint32_t* a,
                                         uint32_t b0, uint32_t b1) {
    asm volatile(
        "mma.sync.aligned.m16n8k16.row.col.f32.bf16.bf16.f32 "
        "{%0,%1,%2,%3}, {%4,%5,%6,%7}, {%8,%9}, {%0,%1,%2,%3};"
        : "+f"(d[0]), "+f"(d[1]), "+f"(d[2]), "+f"(d[3])
        : "r"(a[0]), "r"(a[1]), "r"(a[2]), "r"(a[3]), "r"(b0), "r"(b1));
}

// ---------------------------------------------------------------------------
// fp32 -> split bf16 conversions
// ---------------------------------------------------------------------------
__global__ __launch_bounds__(256) void conv_act(
    const float* __restrict__ in, __nv_bfloat16* __restrict__ out, int nrows)
{
    int i = blockIdx.x * 256 + threadIdx.x;
    if (i >= nrows * 64) return;
    int r = i >> 6, k4 = (i & 63) << 2;
    float4 x = *(const float4*)(in + (size_t)r * 256 + k4);
    alignas(8) __nv_bfloat16 h[4], l[4];
    h[0] = __float2bfloat16(x.x); l[0] = __float2bfloat16(x.x - __bfloat162float(h[0]));
    h[1] = __float2bfloat16(x.y); l[1] = __float2bfloat16(x.y - __bfloat162float(h[1]));
    h[2] = __float2bfloat16(x.z); l[2] = __float2bfloat16(x.z - __bfloat162float(h[2]));
    h[3] = __float2bfloat16(x.w); l[3] = __float2bfloat16(x.w - __bfloat162float(h[3]));
    *(uint2*)(out + (size_t)r * KSPLIT + k4)       = *(uint2*)h;
    *(uint2*)(out + (size_t)r * KSPLIT + 256 + k4) = *(uint2*)l;
}

// W (256 x N) row-major  ->  out (N x 512) K-major split
__global__ __launch_bounds__(256) void conv_wt(
    const float* __restrict__ W, __nv_bfloat16* __restrict__ out, int N)
{
    int i = blockIdx.x * 256 + threadIdx.x;
    if (i >= N * 256) return;
    int n = i >> 8, k = i & 255;
    float x = W[(size_t)k * N + n];
    __nv_bfloat16 h = __float2bfloat16(x);
    out[(size_t)n * KSPLIT + k]       = h;
    out[(size_t)n * KSPLIT + 256 + k] = __float2bfloat16(x - __bfloat162float(h));
}

// ---------------------------------------------------------------------------
// HMMA GEMM body (CTA tile 128x128, 8 warps @ 64x32, bf16 3-term split):
// C[128,128 @ (r0,c0)] = A'[r0:,512] x B'[c0:,512]^T (+bias)
// ---------------------------------------------------------------------------
#define NCHUNK 12
#define STAGE_BYTES 32768
#define GSMEM  (2 * STAGE_BYTES)

__device__ __forceinline__ void gemm_body(
    const __nv_bfloat16* __restrict__ A, const __nv_bfloat16* __restrict__ B,
    const float* __restrict__ bias, float* __restrict__ C, int N,
    int r0, int c0, char* smem)
{
    const uint32_t sb = smem_u32(smem);
    const int tid = threadIdx.x, wid = tid >> 5, lane = tid & 31;
    const int warp_m = wid & 1, warp_n = wid >> 1;

    const int cpRow = tid >> 1;
    const int cpU0  = (tid & 1) * 4;

    auto prefetch = [&](int c, int st) {
        const int p  = c >> 2, kc = c & 3;
        const int ka = ((p == 1) ? 256 : 0) + kc * 64;
        const int kb = ((p == 2) ? 256 : 0) + kc * 64;
        const __nv_bfloat16* ga = A + (size_t)(r0 + cpRow) * KSPLIT + ka + cpU0 * 8;
        const __nv_bfloat16* gb = B + (size_t)(c0 + cpRow) * KSPLIT + kb + cpU0 * 8;
        const uint32_t sa = sb + st * STAGE_BYTES + cpRow * 128;
        const uint32_t sg = sa + 16384;
        const int swz = cpRow & 7;
#pragma unroll
        for (int i = 0; i < 4; i++) {
            const int u = cpU0 + i;
            cp_async16(sa + (((u ^ swz)) << 4), ga + i * 8);
            cp_async16(sg + (((u ^ swz)) << 4), gb + i * 8);
        }
        cp_commit();
    };

    const int r7   = lane & 7;
    const int arow = (lane & 7) | (((lane >> 3) & 1) << 3);
    const int ah   = (lane >> 4) & 1;
    const int brow = (lane & 7) | (((lane >> 4) & 1) << 3);
    const int bh   = (lane >> 3) & 1;

    float acc[4][4][4];
#pragma unroll
    for (int mi = 0; mi < 4; mi++)
#pragma unroll
        for (int ni = 0; ni < 4; ni++)
#pragma unroll
            for (int j = 0; j < 4; j++) acc[mi][ni][j] = 0.f;

    prefetch(0, 0);

    for (int c = 0; c < NCHUNK; c++) {
        const int st = c & 1;
        if (c + 1 < NCHUNK) { prefetch(c + 1, st ^ 1); cp_wait<1>(); }
        else                { cp_wait<0>(); }
        __syncthreads();

        const uint32_t Ast = sb + st * STAGE_BYTES;
        const uint32_t Bst = Ast + 16384;

#pragma unroll
        for (int ks = 0; ks < 4; ks++) {
            uint32_t af[4][4];
#pragma unroll
            for (int mi = 0; mi < 4; mi++) {
                const int row = warp_m * 64 + mi * 16 + arow;
                const uint32_t addr = Ast + row * 128 + (((ks * 2 + ah) ^ r7) << 4);
                ldsm_x4(af[mi][0], af[mi][1], af[mi][2], af[mi][3], addr);
            }
            uint32_t bf[4][2];
#pragma unroll
            for (int nh = 0; nh < 2; nh++) {
                const int row = warp_n * 32 + nh * 16 + brow;
                const uint32_t addr = Bst + row * 128 + (((ks * 2 + bh) ^ r7) << 4);
                uint32_t t0, t1, t2, t3;
                ldsm_x4(t0, t1, t2, t3, addr);
                bf[nh * 2][0] = t0; bf[nh * 2][1] = t1;
                bf[nh * 2 + 1][0] = t2; bf[nh * 2 + 1][1] = t3;
            }
#pragma unroll
            for (int mi = 0; mi < 4; mi++)
#pragma unroll
                for (int ni = 0; ni < 4; ni++)
                    mma16816(acc[mi][ni], af[mi], bf[ni][0], bf[ni][1]);
        }
        __syncthreads();
    }

    const int g = lane >> 2, tig = lane & 3;
    float2 bb[4];
#pragma unroll
    for (int ni = 0; ni < 4; ni++)
        bb[ni] = *(const float2*)(bias + c0 + warp_n * 32 + ni * 8 + tig * 2);
#pragma unroll
    for (int mi = 0; mi < 4; mi++) {
        const int rowg = r0 + warp_m * 64 + mi * 16 + g;
        float* p0 = C + (size_t)rowg * N + c0 + warp_n * 32 + tig * 2;
        float* p1 = p0 + (size_t)8 * N;
#pragma unroll
        for (int ni = 0; ni < 4; ni++) {
            float2 o0 = { acc[mi][ni][0] + bb[ni].x, acc[mi][ni][1] + bb[ni].y };
            float2 o1 = { acc[mi][ni][2] + bb[ni].x, acc[mi][ni][3] + bb[ni].y };
            *(float2*)(p0 + ni * 8) = o0;
            *(float2*)(p1 + ni * 8) = o1;
        }
    }
}

// Fused launch: seg0 value-proj (340 CTAs), seg1 offsets (340), seg2 logits (170)
__global__ __launch_bounds__(256, 2) void gemm_fused3(
    const __nv_bfloat16* __restrict__ Av, const __nv_bfloat16* __restrict__ Aq,
    const __nv_bfloat16* __restrict__ Bv, const __nv_bfloat16* __restrict__ Bo,
    const __nv_bfloat16* __restrict__ Ba,
    const float* __restrict__ bv, const float* __restrict__ bo,
    const float* __restrict__ ba,
    float* __restrict__ Cv, float* __restrict__ Co, float* __restrict__ Ca)
{
    extern __shared__ char smem[];
    int id = blockIdx.x;
    if (id < 340) {
        gemm_body(Av, Bv, bv, Cv, 256, (id >> 1) * 128, (id & 1) * 128, smem);
    } else if (id < 680) {
        id -= 340;
        gemm_body(Aq, Bo, bo, Co, 256, (id >> 1) * 128, (id & 1) * 128, smem);
    } else {
        id -= 680;
        gemm_body(Aq, Ba, ba, Ca, 128, id * 128, 0, smem);
    }
}

__global__ __launch_bounds__(256, 2) void gemm_out(
    const __nv_bfloat16* __restrict__ A, const __nv_bfloat16* __restrict__ B,
    const float* __restrict__ bias, float* __restrict__ C)
{
    extern __shared__ char smem[];
    gemm_body(A, B, bias, C, 256, (blockIdx.x >> 1) * 128, (blockIdx.x & 1) * 128, smem);
}

// ---------------------------------------------------------------------------
// Deformable sampling v2: one warp per (b, q, head).
// Lanes 0-15 process even points, 16-31 odd points; each lane owns a channel
// PAIR (float2). Output written directly as split-bf16 rows of g_Aat.
// ---------------------------------------------------------------------------
__global__ __launch_bounds__(256) void msda_sample(
    const float* __restrict__ v, const float* __restrict__ off,
    const float* __restrict__ aw, const float* __restrict__ ref,
    __nv_bfloat16* __restrict__ outs)   // (B*NQ, 512) = [hi|lo]
{
    const int bq   = blockIdx.x;
    const int head = threadIdx.x >> 5;
    const int lane = threadIdx.x & 31;
    const int b    = bq / NQ;
    const unsigned FULL = 0xffffffffu;

    // ---- softmax over 16 logits ----
    const float* awp = aw + ((size_t)bq * NHEADS + head) * 16;
    const float NEG_INF = __int_as_float(0xff800000u);
    float a = (lane < 16) ? awp[lane] : NEG_INF;
    float m = a;
#pragma unroll
    for (int o = 16; o; o >>= 1) m = fmaxf(m, __shfl_xor_sync(FULL, m, o));
    float e = (lane < 16) ? expf(a - m) : 0.f;
    float s = e;
#pragma unroll
    for (int o = 16; o; o >>= 1) s += __shfl_xor_sync(FULL, s, o);
    const float p = e / s;

    // ---- phase 1: lane j (<16) computes point j's base offset + weights ----
    const float offv = off[(size_t)bq * EMBED + head * 32 + lane];
    const float ox = __shfl_sync(FULL, offv, 2 * lane);
    const float oy = __shfl_sync(FULL, offv, 2 * lane + 1);
    const float refv = (lane < 8) ? ref[(size_t)bq * 8 + lane] : 0.f;
    const int   l  = (lane >> 2) & 3;
    const float rx = __shfl_sync(FULL, refv, 2 * l);
    const float ry = __shfl_sync(FULL, refv, 2 * l + 1);

    const int   Wi  = 64 >> l;
    const float Wf  = (float)Wi;
    const int   cur = (16384 - (16384 >> (2 * l))) / 3;

    const float px = (rx + ox / Wf) * Wf - 0.5f;
    const float py = (ry + oy / Wf) * Wf - 0.5f;
    const float x0f = floorf(px), y0f = floorf(py);
    const float wx = px - x0f,    wy = py - y0f;
    const int x0 = (int)x0f, y0 = (int)y0f;

    const bool vx0 = (x0 >= 0)  & (x0 < Wi);
    const bool vx1 = (x0 >= -1) & (x0 < Wi - 1);
    const bool vy0 = (y0 >= 0)  & (y0 < Wi);
    const bool vy1 = (y0 >= -1) & (y0 < Wi - 1);
    const float u = 1.f - wx, t = 1.f - wy;

    float c00 = (vx0 && vy0) ? p * u  * t  : 0.f;
    float c10 = (vx1 && vy0) ? p * wx * t  : 0.f;
    float c01 = (vx0 && vy1) ? p * u  * wy : 0.f;
    float c11 = (vx1 && vy1) ? p * wx * wy : 0.f;

    int idx = cur + y0 * Wi + x0;
    idx = min(max(idx, -65), NV - 1);
    const int o00 = idx << 10;

    // ---- phase 2: 8 iterations, 2 points each (grp selects even/odd) ----
    const int grp = lane >> 4;          // point parity handled by this lane
    const int hl  = lane & 15;          // channel pair index
    const char* vb = (const char*)(v + (size_t)b * NV * EMBED + head * 32 + hl * 2);

    float ax = 0.f, ay = 0.f;
#pragma unroll
    for (int jp = 0; jp < 8; jp++) {
        const int rowB = (64 >> (jp >> 1)) << 10;     // level = jp>>1
        const int src = 2 * jp + grp;
        const int   io  = __shfl_sync(FULL, o00, src);
        const float w00 = __shfl_sync(FULL, c00, src);
        const float w10 = __shfl_sync(FULL, c10, src);
        const float w01 = __shfl_sync(FULL, c01, src);
        const float w11 = __shfl_sync(FULL, c11, src);
        const char* ad = vb + io;
        const float2 v00 = *(const float2*)(ad);
        const float2 v10 = *(const float2*)(ad + 1024);
        const float2 v01 = *(const float2*)(ad + rowB);
        const float2 v11 = *(const float2*)(ad + rowB + 1024);
        ax = fmaf(w00, v00.x, ax);  ay = fmaf(w00, v00.y, ay);
        ax = fmaf(w10, v10.x, ax);  ay = fmaf(w10, v10.y, ay);
        ax = fmaf(w01, v01.x, ax);  ay = fmaf(w01, v01.y, ay);
        ax = fmaf(w11, v11.x, ax);  ay = fmaf(w11, v11.y, ay);
    }
    // combine even/odd point partial sums
    ax += __shfl_xor_sync(FULL, ax, 16);
    ay += __shfl_xor_sync(FULL, ay, 16);

    // ---- epilogue: split-bf16 write (lanes 0-15 only) ----
    if (grp == 0) {
        __nv_bfloat162 hv, lv;
        hv.x = __float2bfloat16(ax);
        hv.y = __float2bfloat16(ay);
        lv.x = __float2bfloat16(ax - __bfloat162float(hv.x));
        lv.y = __float2bfloat16(ay - __bfloat162float(hv.y));
        const size_t base = (size_t)bq * KSPLIT + head * 32 + hl * 2;
        *(__nv_bfloat162*)(outs + base)       = hv;
        *(__nv_bfloat162*)(outs + base + 256) = lv;
    }
}

// ---------------------------------------------------------------------------
// Launch
// ---------------------------------------------------------------------------
extern "C" void kernel_launch(void* const* d_in, const int* in_sizes, int n_in,
                              void* d_out, int out_size)
{
    const float* query = (const float*)d_in[0];
    const float* value = (const float*)d_in[1];
    const float* refp  = (const float*)d_in[2];
    const float* Wv    = (const float*)d_in[3];
    const float* bv    = (const float*)d_in[4];
    const float* Wo    = (const float*)d_in[5];
    const float* bo    = (const float*)d_in[6];
    const float* Wa    = (const float*)d_in[7];
    const float* ba    = (const float*)d_in[8];
    const float* Wout  = (const float*)d_in[9];
    const float* bout  = (const float*)d_in[10];
    float* out = (float*)d_out;

    float *pvraw, *poff, *paw;
    __nv_bfloat16 *pAv, *pAq, *pAat, *pBv, *pBo, *pBa, *pBout;
    cudaGetSymbolAddress((void**)&pvraw, g_vbuf);
    cudaGetSymbolAddress((void**)&poff,  g_off);
    cudaGetSymbolAddress((void**)&paw,   g_aw);
    cudaGetSymbolAddress((void**)&pAv,   g_Av);
    cudaGetSymbolAddress((void**)&pAq,   g_Aq);
    cudaGetSymbolAddress((void**)&pAat,  g_Aat);
    cudaGetSymbolAddress((void**)&pBv,   g_Bv);
    cudaGetSymbolAddress((void**)&pBo,   g_Bo);
    cudaGetSymbolAddress((void**)&pBa,   g_Ba);
    cudaGetSymbolAddress((void**)&pBout, g_Bout);
    float* pv = pvraw + VPAD;

    cudaFuncSetAttribute(gemm_fused3, cudaFuncAttributeMaxDynamicSharedMemorySize, GSMEM);
    cudaFuncSetAttribute(gemm_out,    cudaFuncAttributeMaxDynamicSharedMemorySize, GSMEM);

    const int gA = (MROWS * 64 + 255) / 256;
    conv_act<<<gA, 256>>>(value, pAv, MROWS);
    conv_act<<<gA, 256>>>(query, pAq, MROWS);
    conv_wt<<<256, 256>>>(Wv,   pBv,   256);
    conv_wt<<<256, 256>>>(Wo,   pBo,   256);
    conv_wt<<<128, 256>>>(Wa,   pBa,   128);
    conv_wt<<<256, 256>>>(Wout, pBout, 256);

    gemm_fused3<<<850, 256, GSMEM>>>(pAv, pAq, pBv, pBo, pBa,
                                     bv, bo, ba, pv, poff, paw);

    msda_sample<<<MROWS, 256>>>(pv, poff, paw, refp, pAat);

    gemm_out<<<340, 256, GSMEM>>>(pAat, pBout, bout, out);
}

// round 9
// speedup vs baseline: 2.1170x; 1.0604x over previous
#include <cuda_runtime.h>
#include <cuda_bf16.h>
#include <cstdint>

// ---------------------------------------------------------------------------
// Problem constants
// ---------------------------------------------------------------------------
#define EMBED   256
#define NHEADS  8
#define BATCH   4
#define NQ      5440
#define NV      5440
#define MROWS   (BATCH * NQ)   // 21760 = 170 * 128
#define KSPLIT  512            // [hi(256) | lo(256)] bf16

// ---------------------------------------------------------------------------
// Scratch (device globals; no allocation allowed)
// ---------------------------------------------------------------------------
#define VPAD    (66 * EMBED)
__device__ float g_vbuf[(size_t)VPAD + (size_t)MROWS * EMBED + (size_t)VPAD];
__device__ float g_off[(size_t)MROWS * EMBED];
__device__ float g_aw [(size_t)MROWS * 128];

__device__ __nv_bfloat16 g_Av [(size_t)MROWS * KSPLIT];  // value  split
__device__ __nv_bfloat16 g_Aq [(size_t)MROWS * KSPLIT];  // query  split
__device__ __nv_bfloat16 g_Aat[(size_t)MROWS * KSPLIT];  // attn-out split (from msda)
__device__ __nv_bfloat16 g_Bv  [256 * KSPLIT];           // weights split (K-major)
__device__ __nv_bfloat16 g_Bo  [256 * KSPLIT];
__device__ __nv_bfloat16 g_Ba  [128 * KSPLIT];
__device__ __nv_bfloat16 g_Bout[256 * KSPLIT];

// ---------------------------------------------------------------------------
// PTX helpers (baseline compute_103-safe)
// ---------------------------------------------------------------------------
__device__ __forceinline__ uint32_t smem_u32(const void* p) {
    uint32_t a;
    asm("{ .reg .u64 t; cvta.to.shared.u64 t, %1; cvt.u32.u64 %0, t; }"
        : "=r"(a) : "l"(p));
    return a;
}
__device__ __forceinline__ void cp_async16(uint32_t dst, const void* src) {
    asm volatile("cp.async.cg.shared.global [%0], [%1], 16;"
                 :: "r"(dst), "l"(src) : "memory");
}
__device__ __forceinline__ void cp_commit() {
    asm volatile("cp.async.commit_group;" ::: "memory");
}
template <int N>
__device__ __forceinline__ void cp_wait() {
    asm volatile("cp.async.wait_group %0;" :: "n"(N) : "memory");
}
__device__ __forceinline__ void ldsm_x4(uint32_t& r0, uint32_t& r1,
                                        uint32_t& r2, uint32_t& r3, uint32_t a) {
    asm volatile("ldmatrix.sync.aligned.m8n8.x4.shared.b16 {%0,%1,%2,%3}, [%4];"
                 : "=r"(r0), "=r"(r1), "=r"(r2), "=r"(r3) : "r"(a));
}
__device__ __forceinline__ void mma16816(float* d, const uint32_t* a,
                                         uint32_t b0, uint32_t b1) {
    asm volatile(
        "mma.sync.aligned.m16n8k16.row.col.f32.bf16.bf16.f32 "
        "{%0,%1,%2,%3}, {%4,%5,%6,%7}, {%8,%9}, {%0,%1,%2,%3};"
        : "+f"(d[0]), "+f"(d[1]), "+f"(d[2]), "+f"(d[3])
        : "r"(a[0]), "r"(a[1]), "r"(a[2]), "r"(a[3]), "r"(b0), "r"(b1));
}

// ---------------------------------------------------------------------------
// Fused fp32 -> split-bf16 conversion (activations + all 4 weight matrices)
// ---------------------------------------------------------------------------
__device__ __forceinline__ void conv_act_body(
    const float* __restrict__ in, __nv_bfloat16* __restrict__ out, int i)
{
    int r = i >> 6, k4 = (i & 63) << 2;
    float4 x = *(const float4*)(in + (size_t)r * 256 + k4);
    alignas(8) __nv_bfloat16 h[4], l[4];
    h[0] = __float2bfloat16(x.x); l[0] = __float2bfloat16(x.x - __bfloat162float(h[0]));
    h[1] = __float2bfloat16(x.y); l[1] = __float2bfloat16(x.y - __bfloat162float(h[1]));
    h[2] = __float2bfloat16(x.z); l[2] = __float2bfloat16(x.z - __bfloat162float(h[2]));
    h[3] = __float2bfloat16(x.w); l[3] = __float2bfloat16(x.w - __bfloat162float(h[3]));
    *(uint2*)(out + (size_t)r * KSPLIT + k4)       = *(uint2*)h;
    *(uint2*)(out + (size_t)r * KSPLIT + 256 + k4) = *(uint2*)l;
}
__device__ __forceinline__ void conv_wt_body(
    const float* __restrict__ W, __nv_bfloat16* __restrict__ out, int N, int i)
{
    int n = i >> 8, k = i & 255;
    float x = W[(size_t)k * N + n];
    __nv_bfloat16 h = __float2bfloat16(x);
    out[(size_t)n * KSPLIT + k]       = h;
    out[(size_t)n * KSPLIT + 256 + k] = __float2bfloat16(x - __bfloat162float(h));
}

// grid segments: [0,5440) value, [5440,10880) query,
// [10880,11136) Wv, [11136,11392) Wo, [11392,11520) Wa, [11520,11776) Wout
__global__ __launch_bounds__(256) void conv_all(
    const float* __restrict__ value, const float* __restrict__ query,
    const float* __restrict__ Wv, const float* __restrict__ Wo,
    const float* __restrict__ Wa, const float* __restrict__ Wout,
    __nv_bfloat16* __restrict__ Av, __nv_bfloat16* __restrict__ Aq,
    __nv_bfloat16* __restrict__ Bv, __nv_bfloat16* __restrict__ Bo,
    __nv_bfloat16* __restrict__ Ba, __nv_bfloat16* __restrict__ Bout)
{
    const int id = blockIdx.x, tid = threadIdx.x;
    if (id < 5440) {
        conv_act_body(value, Av, id * 256 + tid);
    } else if (id < 10880) {
        conv_act_body(query, Aq, (id - 5440) * 256 + tid);
    } else if (id < 11136) {
        conv_wt_body(Wv, Bv, 256, (id - 10880) * 256 + tid);
    } else if (id < 11392) {
        conv_wt_body(Wo, Bo, 256, (id - 11136) * 256 + tid);
    } else if (id < 11520) {
        conv_wt_body(Wa, Ba, 128, (id - 11392) * 256 + tid);
    } else {
        conv_wt_body(Wout, Bout, 256, (id - 11520) * 256 + tid);
    }
}

// ---------------------------------------------------------------------------
// HMMA GEMM body (CTA tile 128x128, 8 warps @ 64x32, bf16 3-term split)
// ---------------------------------------------------------------------------
#define NCHUNK 12
#define STAGE_BYTES 32768
#define GSMEM  (2 * STAGE_BYTES)

__device__ __forceinline__ void gemm_body(
    const __nv_bfloat16* __restrict__ A, const __nv_bfloat16* __restrict__ B,
    const float* __restrict__ bias, float* __restrict__ C, int N,
    int r0, int c0, char* smem)
{
    const uint32_t sb = smem_u32(smem);
    const int tid = threadIdx.x, wid = tid >> 5, lane = tid & 31;
    const int warp_m = wid & 1, warp_n = wid >> 1;

    const int cpRow = tid >> 1;
    const int cpU0  = (tid & 1) * 4;

    auto prefetch = [&](int c, int st) {
        const int p  = c >> 2, kc = c & 3;
        const int ka = ((p == 1) ? 256 : 0) + kc * 64;
        const int kb = ((p == 2) ? 256 : 0) + kc * 64;
        const __nv_bfloat16* ga = A + (size_t)(r0 + cpRow) * KSPLIT + ka + cpU0 * 8;
        const __nv_bfloat16* gb = B + (size_t)(c0 + cpRow) * KSPLIT + kb + cpU0 * 8;
        const uint32_t sa = sb + st * STAGE_BYTES + cpRow * 128;
        const uint32_t sg = sa + 16384;
        const int swz = cpRow & 7;
#pragma unroll
        for (int i = 0; i < 4; i++) {
            const int u = cpU0 + i;
            cp_async16(sa + (((u ^ swz)) << 4), ga + i * 8);
            cp_async16(sg + (((u ^ swz)) << 4), gb + i * 8);
        }
        cp_commit();
    };

    const int r7   = lane & 7;
    const int arow = (lane & 7) | (((lane >> 3) & 1) << 3);
    const int ah   = (lane >> 4) & 1;
    const int brow = (lane & 7) | (((lane >> 4) & 1) << 3);
    const int bh   = (lane >> 3) & 1;

    float acc[4][4][4];
#pragma unroll
    for (int mi = 0; mi < 4; mi++)
#pragma unroll
        for (int ni = 0; ni < 4; ni++)
#pragma unroll
            for (int j = 0; j < 4; j++) acc[mi][ni][j] = 0.f;

    prefetch(0, 0);

    for (int c = 0; c < NCHUNK; c++) {
        const int st = c & 1;
        if (c + 1 < NCHUNK) { prefetch(c + 1, st ^ 1); cp_wait<1>(); }
        else                { cp_wait<0>(); }
        __syncthreads();

        const uint32_t Ast = sb + st * STAGE_BYTES;
        const uint32_t Bst = Ast + 16384;

#pragma unroll
        for (int ks = 0; ks < 4; ks++) {
            uint32_t af[4][4];
#pragma unroll
            for (int mi = 0; mi < 4; mi++) {
                const int row = warp_m * 64 + mi * 16 + arow;
                const uint32_t addr = Ast + row * 128 + (((ks * 2 + ah) ^ r7) << 4);
                ldsm_x4(af[mi][0], af[mi][1], af[mi][2], af[mi][3], addr);
            }
            uint32_t bf[4][2];
#pragma unroll
            for (int nh = 0; nh < 2; nh++) {
                const int row = warp_n * 32 + nh * 16 + brow;
                const uint32_t addr = Bst + row * 128 + (((ks * 2 + bh) ^ r7) << 4);
                uint32_t t0, t1, t2, t3;
                ldsm_x4(t0, t1, t2, t3, addr);
                bf[nh * 2][0] = t0; bf[nh * 2][1] = t1;
                bf[nh * 2 + 1][0] = t2; bf[nh * 2 + 1][1] = t3;
            }
#pragma unroll
            for (int mi = 0; mi < 4; mi++)
#pragma unroll
                for (int ni = 0; ni < 4; ni++)
                    mma16816(acc[mi][ni], af[mi], bf[ni][0], bf[ni][1]);
        }
        __syncthreads();
    }

    const int g = lane >> 2, tig = lane & 3;
    float2 bb[4];
#pragma unroll
    for (int ni = 0; ni < 4; ni++)
        bb[ni] = *(const float2*)(bias + c0 + warp_n * 32 + ni * 8 + tig * 2);
#pragma unroll
    for (int mi = 0; mi < 4; mi++) {
        const int rowg = r0 + warp_m * 64 + mi * 16 + g;
        float* p0 = C + (size_t)rowg * N + c0 + warp_n * 32 + tig * 2;
        float* p1 = p0 + (size_t)8 * N;
#pragma unroll
        for (int ni = 0; ni < 4; ni++) {
            float2 o0 = { acc[mi][ni][0] + bb[ni].x, acc[mi][ni][1] + bb[ni].y };
            float2 o1 = { acc[mi][ni][2] + bb[ni].x, acc[mi][ni][3] + bb[ni].y };
            *(float2*)(p0 + ni * 8) = o0;
            *(float2*)(p1 + ni * 8) = o1;
        }
    }
}

// Fused: seg0 value-proj (340 CTAs), seg1 offsets (340), seg2 logits (170)
__global__ __launch_bounds__(256, 2) void gemm_fused3(
    const __nv_bfloat16* __restrict__ Av, const __nv_bfloat16* __restrict__ Aq,
    const __nv_bfloat16* __restrict__ Bv, const __nv_bfloat16* __restrict__ Bo,
    const __nv_bfloat16* __restrict__ Ba,
    const float* __restrict__ bv, const float* __restrict__ bo,
    const float* __restrict__ ba,
    float* __restrict__ Cv, float* __restrict__ Co, float* __restrict__ Ca)
{
    extern __shared__ char smem[];
    int id = blockIdx.x;
    if (id < 340) {
        gemm_body(Av, Bv, bv, Cv, 256, (id >> 1) * 128, (id & 1) * 128, smem);
    } else if (id < 680) {
        id -= 340;
        gemm_body(Aq, Bo, bo, Co, 256, (id >> 1) * 128, (id & 1) * 128, smem);
    } else {
        id -= 680;
        gemm_body(Aq, Ba, ba, Ca, 128, id * 128, 0, smem);
    }
}

__global__ __launch_bounds__(256, 2) void gemm_out(
    const __nv_bfloat16* __restrict__ A, const __nv_bfloat16* __restrict__ B,
    const float* __restrict__ bias, float* __restrict__ C)
{
    extern __shared__ char smem[];
    gemm_body(A, B, bias, C, 256, (blockIdx.x >> 1) * 128, (blockIdx.x & 1) * 128, smem);
}

// ---------------------------------------------------------------------------
// Deformable sampling v3: one warp per (b, q, head).
// Lane = pg*8 + c4 : pg (0..3) = point slot within iteration, c4 (0..7) =
// channel quad. Each corner gather is float4 x 8 contiguous lanes = exactly
// one 128B L1 wavefront. 4 iterations x 4 parallel points cover 16 points;
// level == iteration index (compile-time row stride).
// Output written directly as split-bf16 rows of g_Aat.
// ---------------------------------------------------------------------------
__global__ __launch_bounds__(256) void msda_sample(
    const float* __restrict__ v, const float* __restrict__ off,
    const float* __restrict__ aw, const float* __restrict__ ref,
    __nv_bfloat16* __restrict__ outs)   // (B*NQ, 512) = [hi|lo]
{
    const int bq   = blockIdx.x;
    const int head = threadIdx.x >> 5;
    const int lane = threadIdx.x & 31;
    const int b    = bq / NQ;
    const unsigned FULL = 0xffffffffu;

    // ---- softmax over 16 logits ----
    const float* awp = aw + ((size_t)bq * NHEADS + head) * 16;
    const float NEG_INF = __int_as_float(0xff800000u);
    float a = (lane < 16) ? awp[lane] : NEG_INF;
    float m = a;
#pragma unroll
    for (int o = 16; o; o >>= 1) m = fmaxf(m, __shfl_xor_sync(FULL, m, o));
    float e = (lane < 16) ? expf(a - m) : 0.f;
    float s = e;
#pragma unroll
    for (int o = 16; o; o >>= 1) s += __shfl_xor_sync(FULL, s, o);
    const float p = e / s;

    // ---- phase 1: lane j (<16) computes point j's base offset + weights ----
    const float offv = off[(size_t)bq * EMBED + head * 32 + lane];
    const float ox = __shfl_sync(FULL, offv, 2 * lane);
    const float oy = __shfl_sync(FULL, offv, 2 * lane + 1);
    const float refv = (lane < 8) ? ref[(size_t)bq * 8 + lane] : 0.f;
    const int   l  = (lane >> 2) & 3;
    const float rx = __shfl_sync(FULL, refv, 2 * l);
    const float ry = __shfl_sync(FULL, refv, 2 * l + 1);

    const int   Wi  = 64 >> l;
    const float Wf  = (float)Wi;
    const int   cur = (16384 - (16384 >> (2 * l))) / 3;

    const float px = (rx + ox / Wf) * Wf - 0.5f;
    const float py = (ry + oy / Wf) * Wf - 0.5f;
    const float x0f = floorf(px), y0f = floorf(py);
    const float wx = px - x0f,    wy = py - y0f;
    const int x0 = (int)x0f, y0 = (int)y0f;

    const bool vx0 = (x0 >= 0)  & (x0 < Wi);
    const bool vx1 = (x0 >= -1) & (x0 < Wi - 1);
    const bool vy0 = (y0 >= 0)  & (y0 < Wi);
    const bool vy1 = (y0 >= -1) & (y0 < Wi - 1);
    const float u = 1.f - wx, t = 1.f - wy;

    float c00 = (vx0 && vy0) ? p * u  * t  : 0.f;
    float c10 = (vx1 && vy0) ? p * wx * t  : 0.f;
    float c01 = (vx0 && vy1) ? p * u  * wy : 0.f;
    float c11 = (vx1 && vy1) ? p * wx * wy : 0.f;

    int idx = cur + y0 * Wi + x0;
    idx = min(max(idx, -65), NV - 1);
    const int o00 = idx << 10;

    // ---- phase 2: 4 iterations, 4 parallel points, float4 channels ----
    const int pg = lane >> 3;           // point slot 0..3
    const int c4 = lane & 7;            // channel quad 0..7
    const char* vb = (const char*)(v + (size_t)b * NV * EMBED + head * 32 + c4 * 4);

    float a0 = 0.f, a1 = 0.f, a2 = 0.f, a3 = 0.f;
#pragma unroll
    for (int it = 0; it < 4; it++) {
        const int rowB = (64 >> it) << 10;        // level == it
        const int src = it * 4 + pg;              // point index
        const int   io  = __shfl_sync(FULL, o00, src);
        const float w00 = __shfl_sync(FULL, c00, src);
        const float w10 = __shfl_sync(FULL, c10, src);
        const float w01 = __shfl_sync(FULL, c01, src);
        const float w11 = __shfl_sync(FULL, c11, src);
        const char* ad = vb + io;
        const float4 v00 = *(const float4*)(ad);
        const float4 v10 = *(const float4*)(ad + 1024);
        const float4 v01 = *(const float4*)(ad + rowB);
        const float4 v11 = *(const float4*)(ad + rowB + 1024);
        a0 = fmaf(w00, v00.x, a0); a1 = fmaf(w00, v00.y, a1);
        a2 = fmaf(w00, v00.z, a2); a3 = fmaf(w00, v00.w, a3);
        a0 = fmaf(w10, v10.x, a0); a1 = fmaf(w10, v10.y, a1);
        a2 = fmaf(w10, v10.z, a2); a3 = fmaf(w10, v10.w, a3);
        a0 = fmaf(w01, v01.x, a0); a1 = fmaf(w01, v01.y, a1);
        a2 = fmaf(w01, v01.z, a2); a3 = fmaf(w01, v01.w, a3);
        a0 = fmaf(w11, v11.x, a0); a1 = fmaf(w11, v11.y, a1);
        a2 = fmaf(w11, v11.z, a2); a3 = fmaf(w11, v11.w, a3);
    }
    // reduce over point slots (lane bits 3,4)
    a0 += __shfl_xor_sync(FULL, a0, 8);  a1 += __shfl_xor_sync(FULL, a1, 8);
    a2 += __shfl_xor_sync(FULL, a2, 8);  a3 += __shfl_xor_sync(FULL, a3, 8);
    a0 += __shfl_xor_sync(FULL, a0, 16); a1 += __shfl_xor_sync(FULL, a1, 16);
    a2 += __shfl_xor_sync(FULL, a2, 16); a3 += __shfl_xor_sync(FULL, a3, 16);

    // ---- epilogue: split-bf16 write (lanes 0-7 only) ----
    if (pg == 0) {
        alignas(8) __nv_bfloat16 h[4], lo[4];
        h[0] = __float2bfloat16(a0); lo[0] = __float2bfloat16(a0 - __bfloat162float(h[0]));
        h[1] = __float2bfloat16(a1); lo[1] = __float2bfloat16(a1 - __bfloat162float(h[1]));
        h[2] = __float2bfloat16(a2); lo[2] = __float2bfloat16(a2 - __bfloat162float(h[2]));
        h[3] = __float2bfloat16(a3); lo[3] = __float2bfloat16(a3 - __bfloat162float(h[3]));
        const size_t base = (size_t)bq * KSPLIT + head * 32 + c4 * 4;
        *(uint2*)(outs + base)       = *(uint2*)h;
        *(uint2*)(outs + base + 256) = *(uint2*)lo;
    }
}

// ---------------------------------------------------------------------------
// Launch (4 launches total)
// ---------------------------------------------------------------------------
extern "C" void kernel_launch(void* const* d_in, const int* in_sizes, int n_in,
                              void* d_out, int out_size)
{
    const float* query = (const float*)d_in[0];
    const float* value = (const float*)d_in[1];
    const float* refp  = (const float*)d_in[2];
    const float* Wv    = (const float*)d_in[3];
    const float* bv    = (const float*)d_in[4];
    const float* Wo    = (const float*)d_in[5];
    const float* bo    = (const float*)d_in[6];
    const float* Wa    = (const float*)d_in[7];
    const float* ba    = (const float*)d_in[8];
    const float* Wout  = (const float*)d_in[9];
    const float* bout  = (const float*)d_in[10];
    float* out = (float*)d_out;

    float *pvraw, *poff, *paw;
    __nv_bfloat16 *pAv, *pAq, *pAat, *pBv, *pBo, *pBa, *pBout;
    cudaGetSymbolAddress((void**)&pvraw, g_vbuf);
    cudaGetSymbolAddress((void**)&poff,  g_off);
    cudaGetSymbolAddress((void**)&paw,   g_aw);
    cudaGetSymbolAddress((void**)&pAv,   g_Av);
    cudaGetSymbolAddress((void**)&pAq,   g_Aq);
    cudaGetSymbolAddress((void**)&pAat,  g_Aat);
    cudaGetSymbolAddress((void**)&pBv,   g_Bv);
    cudaGetSymbolAddress((void**)&pBo,   g_Bo);
    cudaGetSymbolAddress((void**)&pBa,   g_Ba);
    cudaGetSymbolAddress((void**)&pBout, g_Bout);
    float* pv = pvraw + VPAD;

    cudaFuncSetAttribute(gemm_fused3, cudaFuncAttributeMaxDynamicSharedMemorySize, GSMEM);
    cudaFuncSetAttribute(gemm_out,    cudaFuncAttributeMaxDynamicSharedMemorySize, GSMEM);

    conv_all<<<11776, 256>>>(value, query, Wv, Wo, Wa, Wout,
                             pAv, pAq, pBv, pBo, pBa, pBout);

    gemm_fused3<<<850, 256, GSMEM>>>(pAv, pAq, pBv, pBo, pBa,
                                     bv, bo, ba, pv, poff, paw);

    msda_sample<<<MROWS, 256>>>(pv, poff, paw, refp, pAat);

    gemm_out<<<340, 256, GSMEM>>>(pAat, pBout, bout, out);
}